// round 15
// baseline (speedup 1.0000x reference)
#include <cuda_runtime.h>
#include <cuda_fp16.h>
#include <cstdint>

// ============================================================================
// DirectedEdgeEncoder on sm_103 (non-'a' target: mma.sync/ldmatrix only).
//
//   out[e] = relu( xW[row[e]] + edge_attr[e] @ W2^T )
//   xW[n]  = x[n] @ W1^T + b          (phase 0, per node)
//
// GEMMs via m16n8k16 fp16:
//   PHASE 0 (nodes, 2-term):  A=[a_hi|a_lo], B=b_hi
//   PHASE 1 (edges, 1-term):  A=a_hi,        B=b_hi   (rel_err ~2.5e-4 < 1e-3)
//
// Round-11: warp specialization. 4 producer warps (LDG -> fp16 pack -> STS,
// idx staging) feed a double-buffered A tile; 12 consumer warps do
// ldmatrix/MMA/epilogue only. Named-barrier full/empty handshake, bounded
// 1-tile drift, 152 CTAs, M_TILE=192 (12 consumer warps x M32xN64).
// ============================================================================

#define M_TILE   192
#define NT       512
#define BROW     128           // B smem row: 64 fp16 (hi only)
#define NCONS    12            // consumer warps
#define PTHREADS 128           // producer threads (4 warps)

// named barriers (id 0 reserved for __syncthreads)
#define BAR_SYNC(id)   asm volatile("bar.sync %0, 512;"   :: "r"(id) : "memory")
#define BAR_ARRIVE(id) asm volatile("bar.arrive %0, 512;" :: "r"(id) : "memory")
#define FULL_BAR(b)   (1 + (b))
#define EMPTY_BAR(b)  (3 + (b))

__device__ float g_xW[50432 * 128];    // node @ W1^T + b   (25.8 MB)

// ---------------------------------------------------------------------------
__device__ __forceinline__ uint32_t smem_u32(const void* p) {
    uint32_t a;
    asm("{ .reg .u64 t; cvta.to.shared.u64 t, %1; cvt.u32.u64 %0, t; }"
        : "=r"(a) : "l"(p));
    return a;
}

__device__ __forceinline__ void ldmatrix_x4(uint32_t& r0, uint32_t& r1,
                                            uint32_t& r2, uint32_t& r3,
                                            uint32_t addr) {
    asm volatile("ldmatrix.sync.aligned.m8n8.x4.shared.b16 {%0,%1,%2,%3}, [%4];"
                 : "=r"(r0), "=r"(r1), "=r"(r2), "=r"(r3) : "r"(addr));
}

__device__ __forceinline__ void mma_f16(float* c, const uint32_t* a,
                                        uint32_t b0, uint32_t b1) {
    asm volatile(
        "mma.sync.aligned.m16n8k16.row.col.f32.f16.f16.f32 "
        "{%0,%1,%2,%3}, {%4,%5,%6,%7}, {%8,%9}, {%0,%1,%2,%3};"
        : "+f"(c[0]), "+f"(c[1]), "+f"(c[2]), "+f"(c[3])
        : "r"(a[0]), "r"(a[1]), "r"(a[2]), "r"(a[3]), "r"(b0), "r"(b1));
}

__device__ __forceinline__ void split4h(float4 v, uint2& hi, uint2& lo) {
    __half2 h0 = __floats2half2_rn(v.x, v.y);
    __half2 h1 = __floats2half2_rn(v.z, v.w);
    float2 f0 = __half22float2(h0);
    float2 f1 = __half22float2(h1);
    __half2 l0 = __floats2half2_rn(v.x - f0.x, v.y - f0.y);
    __half2 l1 = __floats2half2_rn(v.z - f1.x, v.w - f1.y);
    hi.x = *reinterpret_cast<uint32_t*>(&h0);
    hi.y = *reinterpret_cast<uint32_t*>(&h1);
    lo.x = *reinterpret_cast<uint32_t*>(&l0);
    lo.y = *reinterpret_cast<uint32_t*>(&l1);
}

__device__ __forceinline__ uint2 pack4h(float4 v) {
    __half2 h0 = __floats2half2_rn(v.x, v.y);
    __half2 h1 = __floats2half2_rn(v.z, v.w);
    uint2 hi;
    hi.x = *reinterpret_cast<uint32_t*>(&h0);
    hi.y = *reinterpret_cast<uint32_t*>(&h1);
    return hi;
}

// swizzled 8B store: row r, 128B block blk, 8B slot j (0..15)
__device__ __forceinline__ void sw_store8(char* base, int r, int blk, int j,
                                          uint2 v, int stride) {
    uint32_t off = (uint32_t)r * stride + (uint32_t)blk * 128
                 + ((uint32_t)(((j >> 1) ^ (r & 7))) << 4) + ((j & 1) << 3);
    *(uint2*)(base + off) = v;
}

// ---------------------------------------------------------------------------
// PHASE 0 (TERMS=2): g_xW[r] = x[r] @ W[:, :64]^T + bias
// PHASE 1 (TERMS=1): out[e]  = relu( edge_attr[e] @ W[:, 64:]^T + g_xW[row[e]] )
// ---------------------------------------------------------------------------
template <int PHASE>
__global__ void __launch_bounds__(NT, 1)
gemm_kernel(float* __restrict__ out,
            const float* __restrict__ src,        // x or edge_attr [M,64]
            const void*  __restrict__ eidx,
            const float* __restrict__ W,          // [128,128]
            const float* __restrict__ bias,
            int M_total, int n_tiles) {
    constexpr int TERMS = (PHASE == 0) ? 2 : 1;
    constexpr int AROW  = TERMS * 128;
    // smem offsets (compile-time per phase)
    constexpr int SM_B    = 0;                         // 16384
    constexpr int SM_A0   = 16384;
    constexpr int SM_A1   = SM_A0 + M_TILE * AROW;
    constexpr int SM_IDX0 = SM_A1 + M_TILE * AROW;     // 192 int
    constexpr int SM_IDX1 = SM_IDX0 + 1024;
    constexpr int SM_FLAG = SM_IDX1 + 1024;

    extern __shared__ char smem[];
    const int tid  = threadIdx.x;
    const int wid  = tid >> 5;
    const int lane = tid & 31;
    const uint32_t sb = smem_u32(smem);

    // ---- dtype sniff for edge_index (int64 LE: odd 32-bit words all zero)
    if (PHASE == 1 && tid < 32) {
        unsigned v = 0;
        #pragma unroll
        for (int s = 0; s < 4; s++)
            v |= ((const unsigned*)eidx)[1 + 2 * (tid * 4 + s)];
        unsigned any = __ballot_sync(0xffffffffu, v != 0u);
        if (tid == 0) *(int*)(smem + SM_FLAG) = (any == 0u) ? 1 : 0;
    }

    // ---- build column-permuted B tile (all threads): fp16 hi only
    {
        const float* Wp = W + (PHASE == 0 ? 0 : 64);
        #pragma unroll
        for (int i = 0; i < 4; i++) {
            int idx = i * NT + tid;              // 0..2047
            int ns = idx >> 4;
            int j  = idx & 15;
            int nw   = ns >> 6;
            int rest = ns & 63;
            int ni = rest >> 3, pos = rest & 7;
            int q = pos >> 1, jj = pos & 1;
            int L = nw * 64 + ((ni >> 1) << 4) + (q << 2) + ((ni & 1) << 1) + jj;
            float4 v = *(const float4*)(Wp + L * 128 + j * 4);
            sw_store8(smem + SM_B, ns, 0, j, pack4h(v), BROW);
        }
    }
    __syncthreads();
    const int is64 = (PHASE == 1) ? *(const int*)(smem + SM_FLAG) : 0;

    if (wid >= NCONS) {
        // =================== PRODUCER (4 warps, 128 threads) ===============
        const int ptid = tid - NCONS * 32;       // 0..127
        int parity = 0;

        if (TERMS == 1) {
            // register-prefetched fp16 path (phase 1)
            uint2 fh[24];
            int t0 = blockIdx.x;
            if (t0 < n_tiles) {
                #pragma unroll
                for (int i = 0; i < 24; i++) {
                    int idx = i * PTHREADS + ptid;      // 0..3071
                    int r = idx >> 4, j = idx & 15;
                    int gr = t0 * M_TILE + r;
                    if (gr >= M_total) gr = 0;
                    fh[i] = pack4h(__ldg((const float4*)(src + (size_t)gr * 64
                                                         + j * 4)));
                }
            }
            for (int t = blockIdx.x; t < n_tiles; t += gridDim.x) {
                BAR_SYNC(EMPTY_BAR(parity));
                char* aB = smem + (parity ? SM_A1 : SM_A0);
                #pragma unroll
                for (int i = 0; i < 24; i++) {
                    int idx = i * PTHREADS + ptid;
                    int r = idx >> 4, j = idx & 15;
                    sw_store8(aB, r, 0, j, fh[i], AROW);
                }
                if (PHASE == 1) {
                    int* idx_s = (int*)(smem + (parity ? SM_IDX1 : SM_IDX0));
                    for (int e0 = ptid; e0 < M_TILE; e0 += PTHREADS) {
                        long long e = (long long)t * M_TILE + e0;
                        int r = 0;
                        if (e < M_total)
                            r = is64 ? (int)((const long long*)eidx)[e]
                                     : ((const int*)eidx)[e];
                        idx_s[e0] = r;
                    }
                }
                asm volatile("membar.cta;" ::: "memory");
                BAR_ARRIVE(FULL_BAR(parity));
                // prefetch next tile (latency hidden under next empty-wait)
                int tn = t + gridDim.x;
                if (tn < n_tiles) {
                    #pragma unroll
                    for (int i = 0; i < 24; i++) {
                        int idx = i * PTHREADS + ptid;
                        int r = idx >> 4, j = idx & 15;
                        int gr = tn * M_TILE + r;
                        if (gr >= M_total) gr = 0;
                        fh[i] = pack4h(__ldg((const float4*)
                                             (src + (size_t)gr * 64 + j * 4)));
                    }
                }
                parity ^= 1;
            }
        } else {
            // 2-term path (phase 0): load/split/store in place
            for (int t = blockIdx.x; t < n_tiles; t += gridDim.x) {
                BAR_SYNC(EMPTY_BAR(parity));
                char* aB = smem + (parity ? SM_A1 : SM_A0);
                #pragma unroll
                for (int i = 0; i < 24; i++) {
                    int idx = i * PTHREADS + ptid;
                    int r = idx >> 4, j = idx & 15;
                    int gr = t * M_TILE + r;
                    if (gr >= M_total) gr = 0;
                    float4 v = __ldg((const float4*)(src + (size_t)gr * 64
                                                     + j * 4));
                    uint2 hi, lo;
                    split4h(v, hi, lo);
                    sw_store8(aB, r, 0, j, hi, AROW);
                    sw_store8(aB, r, 1, j, lo, AROW);
                }
                asm volatile("membar.cta;" ::: "memory");
                BAR_ARRIVE(FULL_BAR(parity));
                parity ^= 1;
            }
        }
    } else {
        // =================== CONSUMER (12 warps) ===========================
        BAR_ARRIVE(EMPTY_BAR(0));
        BAR_ARRIVE(EMPTY_BAR(1));

        const int mwarp = wid >> 1;              // 0..5  (32 rows each)
        const int nwarp = wid & 1;               // 0..1  (64 cols each)
        const int q     = lane & 3;

        const int aRow = mwarp * 32 + (lane & 7) + (((lane >> 3) & 1) << 3);
        const uint32_t aRowStride = (uint32_t)aRow * AROW;
        const int aRx = aRow & 7;
        const int aHalf = lane >> 4;
        const int bRowBase = nwarp * 64 + ((lane >> 4) << 3) + (lane & 7);
        const int bHalf = (lane >> 3) & 1;

        float4 bias4[4];
        if (PHASE == 0) {
            #pragma unroll
            for (int p = 0; p < 4; p++)
                bias4[p] = ((const float4*)bias)[nwarp * 16 + p * 4 + q];
        }

        int parity = 0;
        for (int t = blockIdx.x; t < n_tiles; t += gridDim.x) {
            BAR_SYNC(FULL_BAR(parity));
            const uint32_t aRowOff = sb + (parity ? SM_A1 : SM_A0) + aRowStride;

            float acc[2][8][4];
            #pragma unroll
            for (int mi = 0; mi < 2; mi++)
                #pragma unroll
                for (int ni = 0; ni < 8; ni++)
                    #pragma unroll
                    for (int c = 0; c < 4; c++) acc[mi][ni][c] = 0.0f;

            #pragma unroll
            for (int cc = 0; cc < 4; cc++) {
                const int cbase = cc * 2;
                uint32_t ah[2][4], al[2][4];
                #pragma unroll
                for (int mi = 0; mi < 2; mi++) {
                    uint32_t base = aRowOff + (uint32_t)mi * 16 * AROW
                        + ((uint32_t)((cbase + aHalf) ^ aRx) << 4);
                    ldmatrix_x4(ah[mi][0], ah[mi][1], ah[mi][2], ah[mi][3],
                                base);
                    if (TERMS == 2)
                        ldmatrix_x4(al[mi][0], al[mi][1], al[mi][2], al[mi][3],
                                    base + 128);
                }
                uint32_t b[8][2];
                #pragma unroll
                for (int p = 0; p < 4; p++) {
                    int brow = bRowBase + p * 16;
                    uint32_t addr = sb + SM_B + (uint32_t)brow * BROW
                        + ((uint32_t)((cbase + bHalf) ^ (brow & 7)) << 4);
                    ldmatrix_x4(b[2*p][0], b[2*p][1], b[2*p+1][0], b[2*p+1][1],
                                addr);
                }
                #pragma unroll
                for (int mi = 0; mi < 2; mi++)
                    #pragma unroll
                    for (int ni = 0; ni < 8; ni++)
                        mma_f16(acc[mi][ni], ah[mi], b[ni][0], b[ni][1]);
                if (TERMS == 2) {
                    #pragma unroll
                    for (int mi = 0; mi < 2; mi++)
                        #pragma unroll
                        for (int ni = 0; ni < 8; ni++)
                            mma_f16(acc[mi][ni], al[mi], b[ni][0], b[ni][1]);
                }
            }

            // read idx values needed by this warp BEFORE releasing the buffer
            int nd[2][2];
            if (PHASE == 1) {
                const int* idx_s = (const int*)(smem + (parity ? SM_IDX1
                                                               : SM_IDX0));
                #pragma unroll
                for (int mi = 0; mi < 2; mi++) {
                    int r0 = mwarp * 32 + mi * 16 + (lane >> 2);
                    nd[mi][0] = idx_s[r0];
                    nd[mi][1] = idx_s[r0 + 8];
                }
            }
            BAR_ARRIVE(EMPTY_BAR(parity));   // producer may refill now

            // ---- epilogue (overlaps producer refill)
            const int colF4 = nwarp * 16 + q;
            #pragma unroll
            for (int mi = 0; mi < 2; mi++) {
                int r0 = mwarp * 32 + mi * 16 + (lane >> 2);
                int r1 = r0 + 8;
                long long rg0 = (long long)t * M_TILE + r0;
                long long rg1 = (long long)t * M_TILE + r1;
                bool v0 = rg0 < M_total, v1 = rg1 < M_total;
                if (PHASE == 1) {
                    const float4* xp0 = (const float4*)
                        (g_xW + (size_t)nd[mi][0] * 128) + colF4;
                    const float4* xp1 = (const float4*)
                        (g_xW + (size_t)nd[mi][1] * 128) + colF4;
                    float4 g0[4], g1[4];
                    #pragma unroll
                    for (int p = 0; p < 4; p++) { g0[p] = __ldg(xp0 + p * 4);
                                                  g1[p] = __ldg(xp1 + p * 4); }
                    float4* op0 = (float4*)out + (size_t)rg0 * 32 + colF4;
                    float4* op1 = (float4*)out + (size_t)rg1 * 32 + colF4;
                    #pragma unroll
                    for (int p = 0; p < 4; p++) {
                        float4 o;
                        o.x = fmaxf(acc[mi][2*p][0]   + g0[p].x, 0.0f);
                        o.y = fmaxf(acc[mi][2*p][1]   + g0[p].y, 0.0f);
                        o.z = fmaxf(acc[mi][2*p+1][0] + g0[p].z, 0.0f);
                        o.w = fmaxf(acc[mi][2*p+1][1] + g0[p].w, 0.0f);
                        if (v0) op0[p * 4] = o;
                        o.x = fmaxf(acc[mi][2*p][2]   + g1[p].x, 0.0f);
                        o.y = fmaxf(acc[mi][2*p][3]   + g1[p].y, 0.0f);
                        o.z = fmaxf(acc[mi][2*p+1][2] + g1[p].z, 0.0f);
                        o.w = fmaxf(acc[mi][2*p+1][3] + g1[p].w, 0.0f);
                        if (v1) op1[p * 4] = o;
                    }
                } else {
                    float4* op0 = (float4*)g_xW + (size_t)rg0 * 32 + colF4;
                    float4* op1 = (float4*)g_xW + (size_t)rg1 * 32 + colF4;
                    #pragma unroll
                    for (int p = 0; p < 4; p++) {
                        float4 o;
                        o.x = acc[mi][2*p][0]   + bias4[p].x;
                        o.y = acc[mi][2*p][1]   + bias4[p].y;
                        o.z = acc[mi][2*p+1][0] + bias4[p].z;
                        o.w = acc[mi][2*p+1][1] + bias4[p].w;
                        if (v0) op0[p * 4] = o;
                        o.x = acc[mi][2*p][2]   + bias4[p].x;
                        o.y = acc[mi][2*p][3]   + bias4[p].y;
                        o.z = acc[mi][2*p+1][2] + bias4[p].z;
                        o.w = acc[mi][2*p+1][3] + bias4[p].w;
                        if (v1) op1[p * 4] = o;
                    }
                }
            }
            parity ^= 1;
        }
    }
}

// ---------------------------------------------------------------------------
extern "C" void kernel_launch(void* const* d_in, const int* in_sizes, int n_in,
                              void* d_out, int out_size) {
    const float* x         = (const float*)d_in[0];
    const float* edge_attr = (const float*)d_in[1];
    const void*  eidx      = d_in[2];
    const float* W         = (const float*)d_in[3];
    const float* bias      = (const float*)d_in[4];
    float* out             = (float*)d_out;

    const int Nn = in_sizes[0] / 64;
    const int E  = in_sizes[1] / 64;
    const int tiles0 = (Nn + M_TILE - 1) / M_TILE;
    const int tiles1 = (E  + M_TILE - 1) / M_TILE;

    // smem totals per phase (TERMS differ)
    const int smem0 = 16384 + 2 * M_TILE * 256 + 2048 + 16;   // phase 0
    const int smem1 = 16384 + 2 * M_TILE * 128 + 2048 + 16;   // phase 1

    cudaFuncSetAttribute(gemm_kernel<0>,
                         cudaFuncAttributeMaxDynamicSharedMemorySize, smem0);
    cudaFuncSetAttribute(gemm_kernel<1>,
                         cudaFuncAttributeMaxDynamicSharedMemorySize, smem1);

    int grid0 = tiles0 < 152 ? tiles0 : 152;
    gemm_kernel<0><<<grid0, NT, smem0>>>(nullptr, x, eidx, W, bias,
                                         Nn, tiles0);
    int grid1 = tiles1 < 152 ? tiles1 : 152;
    gemm_kernel<1><<<grid1, NT, smem1>>>(out, edge_attr, eidx, W, bias,
                                         E, tiles1);
}

// round 16
// speedup vs baseline: 1.0018x; 1.0018x over previous
#include <cuda_runtime.h>
#include <cuda_fp16.h>
#include <cstdint>

// ============================================================================
// DirectedEdgeEncoder on sm_103 (non-'a' target: mma.sync/ldmatrix only).
//
//   out[e] = relu( xW[row[e]] + edge_attr[e] @ W2^T )
//   xW[n]  = x[n] @ W1^T + b          (phase 0, per node)
//
// GEMMs via m16n8k16 fp16:
//   PHASE 0 (nodes, 2-term):  A=[a_hi|a_lo], B=b_hi
//   PHASE 1 (edges, 1-term):  A=a_hi,        B=b_hi   (rel_err ~2.5e-4 < 1e-3)
//
// Round-12: occupancy attack. NT=768, M_TILE=192, warp tile M32xN32 ->
// acc 32 regs, ~80 regs/thread, 24 warps/SM (was 16). R10 lockstep skeleton
// (2 syncs/tile, LDG->reg prefetch after MMA), grid 152.
// ============================================================================

#define M_TILE   192
#define NT       768
#define BROW     128           // B smem row: 64 fp16 (hi only)

__device__ float g_xW[50432 * 128];    // node @ W1^T + b   (25.8 MB)

// ---------------------------------------------------------------------------
__device__ __forceinline__ uint32_t smem_u32(const void* p) {
    uint32_t a;
    asm("{ .reg .u64 t; cvta.to.shared.u64 t, %1; cvt.u32.u64 %0, t; }"
        : "=r"(a) : "l"(p));
    return a;
}

__device__ __forceinline__ void ldmatrix_x4(uint32_t& r0, uint32_t& r1,
                                            uint32_t& r2, uint32_t& r3,
                                            uint32_t addr) {
    asm volatile("ldmatrix.sync.aligned.m8n8.x4.shared.b16 {%0,%1,%2,%3}, [%4];"
                 : "=r"(r0), "=r"(r1), "=r"(r2), "=r"(r3) : "r"(addr));
}

__device__ __forceinline__ void mma_f16(float* c, const uint32_t* a,
                                        uint32_t b0, uint32_t b1) {
    asm volatile(
        "mma.sync.aligned.m16n8k16.row.col.f32.f16.f16.f32 "
        "{%0,%1,%2,%3}, {%4,%5,%6,%7}, {%8,%9}, {%0,%1,%2,%3};"
        : "+f"(c[0]), "+f"(c[1]), "+f"(c[2]), "+f"(c[3])
        : "r"(a[0]), "r"(a[1]), "r"(a[2]), "r"(a[3]), "r"(b0), "r"(b1));
}

// float4 -> hi (4 fp16) and lo (4 fp16 residuals)
__device__ __forceinline__ void split4h(float4 v, uint2& hi, uint2& lo) {
    __half2 h0 = __floats2half2_rn(v.x, v.y);
    __half2 h1 = __floats2half2_rn(v.z, v.w);
    float2 f0 = __half22float2(h0);
    float2 f1 = __half22float2(h1);
    __half2 l0 = __floats2half2_rn(v.x - f0.x, v.y - f0.y);
    __half2 l1 = __floats2half2_rn(v.z - f1.x, v.w - f1.y);
    hi.x = *reinterpret_cast<uint32_t*>(&h0);
    hi.y = *reinterpret_cast<uint32_t*>(&h1);
    lo.x = *reinterpret_cast<uint32_t*>(&l0);
    lo.y = *reinterpret_cast<uint32_t*>(&l1);
}

__device__ __forceinline__ uint2 pack4h(float4 v) {
    __half2 h0 = __floats2half2_rn(v.x, v.y);
    __half2 h1 = __floats2half2_rn(v.z, v.w);
    uint2 hi;
    hi.x = *reinterpret_cast<uint32_t*>(&h0);
    hi.y = *reinterpret_cast<uint32_t*>(&h1);
    return hi;
}

// swizzled 8B store: row r, 128B block blk, 8B slot j (0..15)
__device__ __forceinline__ void sw_store8(char* base, int r, int blk, int j,
                                          uint2 v, int stride) {
    uint32_t off = (uint32_t)r * stride + (uint32_t)blk * 128
                 + ((uint32_t)(((j >> 1) ^ (r & 7))) << 4) + ((j & 1) << 3);
    *(uint2*)(base + off) = v;
}

// 192 rows x 16 float4 = 3072 items; 4 per thread
__device__ __forceinline__ void load_tile(float4* f, const float* __restrict__ src,
                                          int t, int M_total, int tid) {
    #pragma unroll
    for (int i = 0; i < 4; i++) {
        int idx = i * NT + tid;              // 0..3071
        int r = idx >> 4, j = idx & 15;
        int gr = t * M_TILE + r;
        if (gr >= M_total) gr = 0;           // clamp; stores guarded later
        f[i] = __ldg((const float4*)(src + (size_t)gr * 64 + j * 4));
    }
}

// ---------------------------------------------------------------------------
// PHASE 0 (TERMS=2): g_xW[r] = x[r] @ W[:, :64]^T + bias
// PHASE 1 (TERMS=1): out[e]  = relu( edge_attr[e] @ W[:, 64:]^T + g_xW[row[e]] )
// ---------------------------------------------------------------------------
template <int PHASE>
__global__ void __launch_bounds__(NT, 1)
gemm_kernel(float* __restrict__ out,
            const float* __restrict__ src,        // x or edge_attr [M,64]
            const void*  __restrict__ eidx,
            const float* __restrict__ W,          // [128,128]
            const float* __restrict__ bias,
            int M_total, int n_tiles) {
    constexpr int TERMS = (PHASE == 0) ? 2 : 1;
    constexpr int AROW  = TERMS * 128;       // A smem row bytes
    constexpr int SM_B    = 0;                       // 16384
    constexpr int SM_A    = 16384;
    constexpr int SM_IDX  = SM_A + M_TILE * AROW;    // 192 int
    constexpr int SM_FLAG = SM_IDX + 1024;

    extern __shared__ char smem[];
    const int tid  = threadIdx.x;
    const int wid  = tid >> 5;
    const int lane = tid & 31;
    const uint32_t sb = smem_u32(smem);

    // ---- dtype sniff for edge_index (int64 LE: odd 32-bit words all zero)
    if (PHASE == 1 && tid < 32) {
        unsigned v = 0;
        #pragma unroll
        for (int s = 0; s < 4; s++)
            v |= ((const unsigned*)eidx)[1 + 2 * (tid * 4 + s)];
        unsigned any = __ballot_sync(0xffffffffu, v != 0u);
        if (tid == 0) *(int*)(smem + SM_FLAG) = (any == 0u) ? 1 : 0;
    }

    // ---- build column-permuted B tile: fp16 hi only, N32 warp tiling.
    // smem row ns holds logical W column L(ns) so each thread's accumulator
    // fragments form 4 contiguous logical columns (validated in R5).
    {
        const float* Wp = W + (PHASE == 0 ? 0 : 64);
        #pragma unroll
        for (int i = 0; i < 3; i++) {
            int idx = i * NT + tid;              // 0..2303 (guard at 2048)
            if (idx < 2048) {
                int ns = idx >> 4;               // B smem row 0..127
                int j  = idx & 15;
                int nwq  = ns >> 5;              // N-warp 0..3
                int rest = ns & 31;
                int ni = rest >> 3, pos = rest & 7;
                int q = pos >> 1, jj = pos & 1;
                int L = nwq * 32 + ((ni >> 1) << 4) + (q << 2)
                      + ((ni & 1) << 1) + jj;
                float4 v = *(const float4*)(Wp + L * 128 + j * 4);
                sw_store8(smem + SM_B, ns, 0, j, pack4h(v), BROW);
            }
        }
    }

    // ---- prologue: load first tile into registers
    float4 f[4];
    if (blockIdx.x < n_tiles) load_tile(f, src, blockIdx.x, M_total, tid);
    __syncthreads();

    const int is64 = (PHASE == 1) ? *(const int*)(smem + SM_FLAG) : 0;

    const int mwarp = wid >> 2;              // 0..5  (32 rows each)
    const int nwarp = wid & 3;               // 0..3  (32 logical cols each)
    const int q     = lane & 3;

    const int aRow = mwarp * 32 + (lane & 7) + (((lane >> 3) & 1) << 3);
    const uint32_t aRowOff = sb + SM_A + (uint32_t)aRow * AROW;
    const int aRx = aRow & 7;
    const int aHalf = lane >> 4;
    const int bRowBase = nwarp * 32 + ((lane >> 4) << 3) + (lane & 7);
    const int bHalf = (lane >> 3) & 1;

    float4 bias4[2];
    if (PHASE == 0) {
        #pragma unroll
        for (int p = 0; p < 2; p++)
            bias4[p] = ((const float4*)bias)[nwarp * 8 + p * 4 + q];
    }

    int* idx_s = (int*)(smem + SM_IDX);

    for (int t = blockIdx.x; t < n_tiles; t += gridDim.x) {
        // ---- convert regs -> A tile: fp16 hi (+ lo if TERMS==2)
        {
            const int j = tid & 15;
            #pragma unroll
            for (int i = 0; i < 4; i++) {
                int r = i * 48 + (tid >> 4);
                if (TERMS == 2) {
                    uint2 hi, lo;
                    split4h(f[i], hi, lo);
                    sw_store8(smem + SM_A, r, 0, j, hi, AROW);
                    sw_store8(smem + SM_A, r, 1, j, lo, AROW);
                } else {
                    sw_store8(smem + SM_A, r, 0, j, pack4h(f[i]), AROW);
                }
            }
        }
        if (PHASE == 1 && tid < M_TILE) {
            long long e = (long long)t * M_TILE + tid;
            int r = 0;
            if (e < M_total)
                r = is64 ? (int)((const long long*)eidx)[e]
                         : ((const int*)eidx)[e];
            idx_s[tid] = r;
        }
        __syncthreads();

        // ---- MMA: warp tile M32 x N32
        float acc[2][4][4];
        #pragma unroll
        for (int mi = 0; mi < 2; mi++)
            #pragma unroll
            for (int ni = 0; ni < 4; ni++)
                #pragma unroll
                for (int c = 0; c < 4; c++) acc[mi][ni][c] = 0.0f;

        #pragma unroll
        for (int cc = 0; cc < 4; cc++) {
            const int cbase = cc * 2;
            uint32_t ah[2][4], al[2][4];
            #pragma unroll
            for (int mi = 0; mi < 2; mi++) {
                uint32_t base = aRowOff + (uint32_t)mi * 16 * AROW
                    + ((uint32_t)((cbase + aHalf) ^ aRx) << 4);
                ldmatrix_x4(ah[mi][0], ah[mi][1], ah[mi][2], ah[mi][3], base);
                if (TERMS == 2)
                    ldmatrix_x4(al[mi][0], al[mi][1], al[mi][2], al[mi][3],
                                base + 128);
            }
            uint32_t b[4][2];
            #pragma unroll
            for (int p = 0; p < 2; p++) {
                int brow = bRowBase + p * 16;
                uint32_t addr = sb + SM_B + (uint32_t)brow * BROW
                    + ((uint32_t)((cbase + bHalf) ^ (brow & 7)) << 4);
                ldmatrix_x4(b[2*p][0], b[2*p][1], b[2*p+1][0], b[2*p+1][1],
                            addr);
            }
            #pragma unroll
            for (int mi = 0; mi < 2; mi++)
                #pragma unroll
                for (int ni = 0; ni < 4; ni++)
                    mma_f16(acc[mi][ni], ah[mi], b[ni][0], b[ni][1]);
            if (TERMS == 2) {
                #pragma unroll
                for (int mi = 0; mi < 2; mi++)
                    #pragma unroll
                    for (int ni = 0; ni < 4; ni++)
                        mma_f16(acc[mi][ni], al[mi], b[ni][0], b[ni][1]);
            }
        }

        // ---- prefetch next tile (LDG hidden under epilogue)
        int tn = t + gridDim.x;
        if (tn < n_tiles) load_tile(f, src, tn, M_total, tid);

        // ---- epilogue: float4 fragments at logical cols nwarp*32+16p+4q
        const int colF4 = nwarp * 8 + q;
        #pragma unroll
        for (int mi = 0; mi < 2; mi++) {
            int r0 = mwarp * 32 + mi * 16 + (lane >> 2);
            int r1 = r0 + 8;
            long long rg0 = (long long)t * M_TILE + r0;
            long long rg1 = (long long)t * M_TILE + r1;
            bool v0 = rg0 < M_total, v1 = rg1 < M_total;
            if (PHASE == 1) {
                const float4* xp0 = (const float4*)
                    (g_xW + (size_t)idx_s[r0] * 128) + colF4;
                const float4* xp1 = (const float4*)
                    (g_xW + (size_t)idx_s[r1] * 128) + colF4;
                float4 g0[2], g1[2];
                #pragma unroll
                for (int p = 0; p < 2; p++) { g0[p] = __ldg(xp0 + p * 4);
                                              g1[p] = __ldg(xp1 + p * 4); }
                float4* op0 = (float4*)out + (size_t)rg0 * 32 + colF4;
                float4* op1 = (float4*)out + (size_t)rg1 * 32 + colF4;
                #pragma unroll
                for (int p = 0; p < 2; p++) {
                    float4 o;
                    o.x = fmaxf(acc[mi][2*p][0]   + g0[p].x, 0.0f);
                    o.y = fmaxf(acc[mi][2*p][1]   + g0[p].y, 0.0f);
                    o.z = fmaxf(acc[mi][2*p+1][0] + g0[p].z, 0.0f);
                    o.w = fmaxf(acc[mi][2*p+1][1] + g0[p].w, 0.0f);
                    if (v0) op0[p * 4] = o;
                    o.x = fmaxf(acc[mi][2*p][2]   + g1[p].x, 0.0f);
                    o.y = fmaxf(acc[mi][2*p][3]   + g1[p].y, 0.0f);
                    o.z = fmaxf(acc[mi][2*p+1][2] + g1[p].z, 0.0f);
                    o.w = fmaxf(acc[mi][2*p+1][3] + g1[p].w, 0.0f);
                    if (v1) op1[p * 4] = o;
                }
            } else {
                float4* op0 = (float4*)g_xW + (size_t)rg0 * 32 + colF4;
                float4* op1 = (float4*)g_xW + (size_t)rg1 * 32 + colF4;
                #pragma unroll
                for (int p = 0; p < 2; p++) {
                    float4 o;
                    o.x = acc[mi][2*p][0]   + bias4[p].x;
                    o.y = acc[mi][2*p][1]   + bias4[p].y;
                    o.z = acc[mi][2*p+1][0] + bias4[p].z;
                    o.w = acc[mi][2*p+1][1] + bias4[p].w;
                    if (v0) op0[p * 4] = o;
                    o.x = acc[mi][2*p][2]   + bias4[p].x;
                    o.y = acc[mi][2*p][3]   + bias4[p].y;
                    o.z = acc[mi][2*p+1][2] + bias4[p].z;
                    o.w = acc[mi][2*p+1][3] + bias4[p].w;
                    if (v1) op1[p * 4] = o;
                }
            }
        }
        __syncthreads();   // all reads of A done before next conversion
    }
}

// ---------------------------------------------------------------------------
extern "C" void kernel_launch(void* const* d_in, const int* in_sizes, int n_in,
                              void* d_out, int out_size) {
    const float* x         = (const float*)d_in[0];
    const float* edge_attr = (const float*)d_in[1];
    const void*  eidx      = d_in[2];
    const float* W         = (const float*)d_in[3];
    const float* bias      = (const float*)d_in[4];
    float* out             = (float*)d_out;

    const int Nn = in_sizes[0] / 64;
    const int E  = in_sizes[1] / 64;
    const int tiles0 = (Nn + M_TILE - 1) / M_TILE;
    const int tiles1 = (E  + M_TILE - 1) / M_TILE;

    const int smem0 = 16384 + M_TILE * 256 + 1024 + 16;   // phase 0 (2-term)
    const int smem1 = 16384 + M_TILE * 128 + 1024 + 16;   // phase 1 (1-term)

    cudaFuncSetAttribute(gemm_kernel<0>,
                         cudaFuncAttributeMaxDynamicSharedMemorySize, smem0);
    cudaFuncSetAttribute(gemm_kernel<1>,
                         cudaFuncAttributeMaxDynamicSharedMemorySize, smem1);

    int grid0 = tiles0 < 152 ? tiles0 : 152;
    gemm_kernel<0><<<grid0, NT, smem0>>>(nullptr, x, eidx, W, bias,
                                         Nn, tiles0);
    int grid1 = tiles1 < 152 ? tiles1 : 152;
    gemm_kernel<1><<<grid1, NT, smem1>>>(out, edge_attr, eidx, W, bias,
                                         E, tiles1);
}